// round 14
// baseline (speedup 1.0000x reference)
#include <cuda_runtime.h>
#include <cuda_bf16.h>

// Multilevel DB4 DWT (11 levels), WARP-AUTONOMOUS cascade.
// 512 threads = 16 warps per row; warp w owns x[256w..256w+256).
// All cross-warp boundary values for levels 0-3 are precomputed from x
// directly (lane-distributed recompute chain), so levels 0-3 need NO
// __syncthreads -- only warp shuffles. Single barrier before the 256-pt
// tail (levels 4-10, warp 0). Streaming hints on the bulk I/O.
//
// Boundary (matches reference W[:L,:L] slicing):
//   level 0 : periodic wrap; level >=1: taps beyond L are zero.

#define DWT_N 4096
#define NTH   512
#define FULL  0xffffffffu

__device__ __forceinline__ void dwt_pair(float x0, float x1, float x2, float x3,
                                         float& a, float& d)
{
    const float c0 =  0.4829629131445341f;
    const float c1 =  0.8365163037378079f;
    const float c2 =  0.2241438680420134f;
    const float c3 = -0.1294095225512604f;
    a = c0 * x0 + c1 * x1 + c2 * x2 + c3 * x3;
    d = c3 * x0 - c2 * x1 + c1 * x2 - c0 * x3;
}

__global__ __launch_bounds__(NTH, 3)
void dwt_db4_warp_kernel(const float* __restrict__ in,
                         float* __restrict__ out)
{
    __shared__ float sm4[256];     // tail signal (levels 4-10)

    const int t    = threadIdx.x;
    const int w    = t >> 5;       // warp id 0..15
    const int lane = t & 31;
    const float* src = in  + (size_t)blockIdx.x * DWT_N;
    float*       dst = out + (size_t)blockIdx.x * DWT_N;

    // ---- main load: x[8t..8t+8), 2x LDG.128 streaming ----
    float v[8];
    {
        const float4* s4 = reinterpret_cast<const float4*>(src) + 2 * t;
        float4 f0 = __ldcs(s4);
        float4 f1 = __ldcs(s4 + 1);
        v[0]=f0.x; v[1]=f0.y; v[2]=f0.z; v[3]=f0.w;
        v[4]=f1.x; v[5]=f1.y; v[6]=f1.z; v[7]=f1.w;
    }

    // ---- boundary pre-compute from next segment xn = x[256(w+1)+i] ----
    // a0_b[l] (lane l, l<14) = a0 at signal idx 128(w+1)+l
    // a1_b[l] (lane l, l<6)  = a1 at signal idx  64(w+1)+l
    // a2_b[l] (lane l, l<2)  = a2 at signal idx  32(w+1)+l
    // For w==15 all boundary a's are zero (W[:L,:L] truncation); the
    // level-0 wrap values x[0],x[1] are loaded on lane 0.
    float a0_b = 0.f, a1_b = 0.f, a2_b = 0.f;
    float x0n = 0.f, x1n = 0.f;
    if (w < 15) {
        if (lane < 14) {
            const float* xn = src + 256 * (w + 1);
            float2 p0 = *reinterpret_cast<const float2*>(xn + 2 * lane);
            float2 p1 = *reinterpret_cast<const float2*>(xn + 2 * lane + 2);
            float dd;
            dwt_pair(p0.x, p0.y, p1.x, p1.y, a0_b, dd);
            if (lane == 0) { x0n = p0.x; x1n = p0.y; }
        }
    } else if (lane == 0) {
        float2 p = *reinterpret_cast<const float2*>(src);   // wrap to row start
        x0n = p.x; x1n = p.y;
    }
    // fold a0_b -> a1_b (lanes 0..5)
    {
        float q0 = __shfl_sync(FULL, a0_b, (2*lane)     & 31);
        float q1 = __shfl_sync(FULL, a0_b, (2*lane + 1) & 31);
        float q2 = __shfl_sync(FULL, a0_b, (2*lane + 2) & 31);
        float q3 = __shfl_sync(FULL, a0_b, (2*lane + 3) & 31);
        if (lane < 6) { float dd; dwt_pair(q0, q1, q2, q3, a1_b, dd); }
    }
    // fold a1_b -> a2_b (lanes 0..1)
    {
        float q0 = __shfl_sync(FULL, a1_b, (2*lane)     & 31);
        float q1 = __shfl_sync(FULL, a1_b, (2*lane + 1) & 31);
        float q2 = __shfl_sync(FULL, a1_b, (2*lane + 2) & 31);
        float q3 = __shfl_sync(FULL, a1_b, (2*lane + 3) & 31);
        if (lane < 2) { float dd; dwt_pair(q0, q1, q2, q3, a2_b, dd); }
    }

    // ================= level 0 (L=4096): periodic wrap =================
    float nx0 = __shfl_down_sync(FULL, v[0], 1);
    float nx1 = __shfl_down_sync(FULL, v[1], 1);
    {
        float bx0 = __shfl_sync(FULL, x0n, 0);
        float bx1 = __shfl_sync(FULL, x1n, 0);
        if (lane == 31) { nx0 = bx0; nx1 = bx1; }
    }
    float a0[4], d0[4];
    dwt_pair(v[0], v[1], v[2], v[3], a0[0], d0[0]);
    dwt_pair(v[2], v[3], v[4], v[5], a0[1], d0[1]);
    dwt_pair(v[4], v[5], v[6], v[7], a0[2], d0[2]);
    dwt_pair(v[6], v[7], nx0,  nx1,  a0[3], d0[3]);
    __stcs(reinterpret_cast<float4*>(dst + 2048 + 4 * t),
           make_float4(d0[0], d0[1], d0[2], d0[3]));

    // ================= level 1 (L=2048): truncated =================
    float na0 = __shfl_down_sync(FULL, a0[0], 1);
    float na1 = __shfl_down_sync(FULL, a0[1], 1);
    {
        float b0 = __shfl_sync(FULL, a0_b, 0);
        float b1 = __shfl_sync(FULL, a0_b, 1);
        if (lane == 31) { na0 = b0; na1 = b1; }
    }
    float a1[2], d1[2];
    dwt_pair(a0[0], a0[1], a0[2], a0[3], a1[0], d1[0]);
    dwt_pair(a0[2], a0[3], na0,   na1,   a1[1], d1[1]);
    __stcs(reinterpret_cast<float2*>(dst + 1024 + 2 * t),
           make_float2(d1[0], d1[1]));

    // ================= level 2 (L=1024): truncated =================
    float nb0 = __shfl_down_sync(FULL, a1[0], 1);
    float nb1 = __shfl_down_sync(FULL, a1[1], 1);
    {
        float b0 = __shfl_sync(FULL, a1_b, 0);
        float b1 = __shfl_sync(FULL, a1_b, 1);
        if (lane == 31) { nb0 = b0; nb1 = b1; }
    }
    float a2, d2;
    dwt_pair(a1[0], a1[1], nb0, nb1, a2, d2);
    __stcs(dst + 512 + t, d2);

    // ================= level 3 (L=512): truncated =================
    // lanes 0..15 compute a3/d3 at signal idx 16w+lane from a2 of
    // lanes 2l..2l+3 (lane 15 borrows a2_b[0..2) from the boundary chain).
    {
        float c0 = __shfl_sync(FULL, a2, (2*lane)     & 31);
        float c1 = __shfl_sync(FULL, a2, (2*lane + 1) & 31);
        float c2 = __shfl_sync(FULL, a2, (2*lane + 2) & 31);
        float c3 = __shfl_sync(FULL, a2, (2*lane + 3) & 31);
        float ab0 = __shfl_sync(FULL, a2_b, 0);
        float ab1 = __shfl_sync(FULL, a2_b, 1);
        if (lane == 15) { c2 = ab0; c3 = ab1; }
        if (lane < 16) {
            float a3, d3;
            dwt_pair(c0, c1, c2, c3, a3, d3);
            __stcs(dst + 256 + 16 * w + lane, d3);
            sm4[16 * w + lane] = a3;
        }
    }
    __syncthreads();

    // ================= levels 4-10 on sm4[0:256): warp 0 ================
    if (t < 32) {
        #pragma unroll
        for (int l = 0; l < 7; ++l) {
            const int L = 256 >> l;
            const int H = L >> 1;
            float ra[4], rd[4];
            int cnt = 0;
            #pragma unroll
            for (int k = t; k < H; k += 32) {
                float x0 = sm4[2*k],     x1 = sm4[2*k + 1];
                float x2 = (2*k + 2 < L) ? sm4[2*k + 2] : 0.f;
                float x3 = (2*k + 3 < L) ? sm4[2*k + 3] : 0.f;
                dwt_pair(x0, x1, x2, x3, ra[cnt], rd[cnt]);
                ++cnt;
            }
            __syncwarp();
            cnt = 0;
            #pragma unroll
            for (int k = t; k < H; k += 32) {
                sm4[k]     = ra[cnt];
                sm4[H + k] = rd[cnt];
                ++cnt;
            }
            __syncwarp();
        }
        // out[0:256) final
        #pragma unroll
        for (int i = t; i < 64; i += 32)
            __stcs(reinterpret_cast<float4*>(dst) + i,
                   reinterpret_cast<const float4*>(sm4)[i]);
    }
}

extern "C" void kernel_launch(void* const* d_in, const int* in_sizes, int n_in,
                              void* d_out, int out_size)
{
    const float* x = (const float*)d_in[0];   // [B, N] float32
    // d_in[1] = W : structure known analytically; unused.
    float* out = (float*)d_out;

    const int B = in_sizes[0] / DWT_N;        // 4096 rows
    dwt_db4_warp_kernel<<<B, NTH>>>(x, out);
}

// round 15
// speedup vs baseline: 1.0658x; 1.0658x over previous
#include <cuda_runtime.h>
#include <cuda_bf16.h>

// Multilevel DB4 DWT (11 levels), register cascade, FOUR rows per CTA.
// 512 threads/CTA; thread t owns x[8t..8t+8) of rows 4b..4b+3.
// All 8 row-loads issued back-to-back before the first barrier; the 5
// __syncthreads amortized over 4 rows; level 3 uses 128 threads/row and
// tail levels 4-10 run on warps 0-3 (one row each) concurrently.
// Streaming hints (__ldcs/__stcs) on all bulk global I/O.
//
// Boundary (matches reference W[:L,:L] slicing):
//   level 0 : periodic wrap; level >=1: taps beyond L are zero.

#define DWT_N 4096
#define NTH   512
#define NROW  4

__device__ __forceinline__ void dwt_pair(float x0, float x1, float x2, float x3,
                                         float& a, float& d)
{
    const float c0 =  0.4829629131445341f;
    const float c1 =  0.8365163037378079f;
    const float c2 =  0.2241438680420134f;
    const float c3 = -0.1294095225512604f;
    a = c0 * x0 + c1 * x1 + c2 * x2 + c3 * x3;
    d = c3 * x0 - c2 * x1 + c1 * x2 - c0 * x3;
}

__global__ __launch_bounds__(NTH, 2)
void dwt_db4_4row_kernel(const float* __restrict__ in,
                         float* __restrict__ out)
{
    __shared__ float exA[NROW * 2 * NTH];   // exchange ping (16KB)
    __shared__ float exB[NROW * 2 * NTH];   // exchange pong (16KB)
    __shared__ float sm3[NROW][NTH];        // level-3 inputs (8KB)
    __shared__ float sm4[NROW][256];        // levels 4-10 signals (4KB)

    const int t = threadIdx.x;
    const size_t row0 = (size_t)NROW * blockIdx.x;
    const float* src[NROW];
    float*       dst[NROW];
    #pragma unroll
    for (int r = 0; r < NROW; ++r) {
        src[r] = in  + (row0 + r) * DWT_N;
        dst[r] = out + (row0 + r) * DWT_N;
    }

    // ---- 8 back-to-back LDG.128 (streaming): all 4 rows in flight ----
    float v[NROW][8];
    #pragma unroll
    for (int r = 0; r < NROW; ++r) {
        const float4* s4 = reinterpret_cast<const float4*>(src[r]) + 2 * t;
        float4 f0 = __ldcs(s4);
        float4 f1 = __ldcs(s4 + 1);
        v[r][0]=f0.x; v[r][1]=f0.y; v[r][2]=f0.z; v[r][3]=f0.w;
        v[r][4]=f1.x; v[r][5]=f1.y; v[r][6]=f1.z; v[r][7]=f1.w;
    }

    // ================= level 0 (L=4096): periodic wrap =================
    #pragma unroll
    for (int r = 0; r < NROW; ++r)
        *reinterpret_cast<float2*>(&exA[r * 2 * NTH + 2 * t]) =
            make_float2(v[r][0], v[r][1]);
    __syncthreads();

    float a0[NROW][4];
    {
        const int tn = 2 * ((t + 1) & (NTH - 1));
        #pragma unroll
        for (int r = 0; r < NROW; ++r) {
            float2 nb = *reinterpret_cast<const float2*>(&exA[r * 2 * NTH + tn]);
            float d0[4];
            dwt_pair(v[r][0], v[r][1], v[r][2], v[r][3], a0[r][0], d0[0]);
            dwt_pair(v[r][2], v[r][3], v[r][4], v[r][5], a0[r][1], d0[1]);
            dwt_pair(v[r][4], v[r][5], v[r][6], v[r][7], a0[r][2], d0[2]);
            dwt_pair(v[r][6], v[r][7], nb.x,    nb.y,    a0[r][3], d0[3]);
            __stcs(reinterpret_cast<float4*>(dst[r] + 2048 + 4 * t),
                   make_float4(d0[0], d0[1], d0[2], d0[3]));
        }
    }

    // ================= level 1 (L=2048): truncated =================
    #pragma unroll
    for (int r = 0; r < NROW; ++r)
        *reinterpret_cast<float2*>(&exB[r * 2 * NTH + 2 * t]) =
            make_float2(a0[r][0], a0[r][1]);
    __syncthreads();

    float a1[NROW][2];
    #pragma unroll
    for (int r = 0; r < NROW; ++r) {
        float2 nb = (t == NTH - 1)
            ? make_float2(0.f, 0.f)
            : *reinterpret_cast<const float2*>(&exB[r * 2 * NTH + 2 * (t + 1)]);
        float d1[2];
        dwt_pair(a0[r][0], a0[r][1], a0[r][2], a0[r][3], a1[r][0], d1[0]);
        dwt_pair(a0[r][2], a0[r][3], nb.x,     nb.y,     a1[r][1], d1[1]);
        __stcs(reinterpret_cast<float2*>(dst[r] + 1024 + 2 * t),
               make_float2(d1[0], d1[1]));
    }

    // ================= level 2 (L=1024): truncated =================
    #pragma unroll
    for (int r = 0; r < NROW; ++r)
        *reinterpret_cast<float2*>(&exA[r * 2 * NTH + 2 * t]) =
            make_float2(a1[r][0], a1[r][1]);
    __syncthreads();

    #pragma unroll
    for (int r = 0; r < NROW; ++r) {
        float2 nb = (t == NTH - 1)
            ? make_float2(0.f, 0.f)
            : *reinterpret_cast<const float2*>(&exA[r * 2 * NTH + 2 * (t + 1)]);
        float a2, d2;
        dwt_pair(a1[r][0], a1[r][1], nb.x, nb.y, a2, d2);
        __stcs(dst[r] + 512 + t, d2);
        sm3[r][t] = a2;
    }
    __syncthreads();

    // ========== level 3 (L=512): 128 threads per row, 2 outputs each =====
    {
        const int r  = t >> 7;          // row 0..3
        const int k2 = t & 127;         // 2 outputs: k = 2*k2, 2*k2+1
        float* drow = dst[r];
        const float* s = sm3[r];

        float a3[2], d3[2];
        // k = 2*k2 : taps s[4k2 .. 4k2+3]
        dwt_pair(s[4*k2], s[4*k2+1], s[4*k2+2], s[4*k2+3], a3[0], d3[0]);
        // k = 2*k2+1 : taps s[4k2+2 .. 4k2+5], zero-pad at end
        float x2 = (4*k2 + 4 < 512) ? s[4*k2 + 4] : 0.f;
        float x3 = (4*k2 + 5 < 512) ? s[4*k2 + 5] : 0.f;
        dwt_pair(s[4*k2+2], s[4*k2+3], x2, x3, a3[1], d3[1]);

        __stcs(reinterpret_cast<float2*>(drow + 256 + 2 * k2),
               make_float2(d3[0], d3[1]));
        sm4[r][2*k2]     = a3[0];
        sm4[r][2*k2 + 1] = a3[1];
    }
    __syncthreads();

    // ===== levels 4-10: warps 0-3, one row each, concurrent =============
    if (t < 4 * 32) {
        const int r    = t >> 5;
        const int lane = t & 31;
        float* srow = sm4[r];
        float* drow = dst[r];

        #pragma unroll
        for (int l = 0; l < 7; ++l) {
            const int L = 256 >> l;
            const int H = L >> 1;
            float ra[4], rd[4];
            int cnt = 0;
            #pragma unroll
            for (int k = lane; k < H; k += 32) {
                float x0 = srow[2*k],     x1 = srow[2*k + 1];
                float x2 = (2*k + 2 < L) ? srow[2*k + 2] : 0.f;
                float x3 = (2*k + 3 < L) ? srow[2*k + 3] : 0.f;
                dwt_pair(x0, x1, x2, x3, ra[cnt], rd[cnt]);
                ++cnt;
            }
            __syncwarp();
            cnt = 0;
            #pragma unroll
            for (int k = lane; k < H; k += 32) {
                srow[k]     = ra[cnt];
                srow[H + k] = rd[cnt];
                ++cnt;
            }
            __syncwarp();
        }
        // out[0:256) final
        #pragma unroll
        for (int i = lane; i < 64; i += 32)
            __stcs(reinterpret_cast<float4*>(drow) + i,
                   reinterpret_cast<const float4*>(srow)[i]);
    }
}

extern "C" void kernel_launch(void* const* d_in, const int* in_sizes, int n_in,
                              void* d_out, int out_size)
{
    const float* x = (const float*)d_in[0];   // [B, N] float32
    // d_in[1] = W : structure known analytically; unused.
    float* out = (float*)d_out;

    const int B = in_sizes[0] / DWT_N;        // 4096 rows
    dwt_db4_4row_kernel<<<B / NROW, NTH>>>(x, out);
}